// round 12
// baseline (speedup 1.0000x reference)
#include <cuda_runtime.h>
#include <cuda_bf16.h>
#include <math.h>
#include <stdint.h>

// ---------------- problem constants ----------------
#define Bb 2
#define Tt 2048
#define Cc 1024
#define Hh 16
#define DH 64
#define BT (Bb*Tt)            // 4096
#define C3 (3*Cc)             // 3072
#define BH (Bb*Hh)            // 32

// output buffer layout (flatten-concat of the reference tuple, fp32)
#define N_OUT   ((size_t)Bb*Tt*Cc)                 // 4,194,304
#define OFF_DE  (N_OUT)
#define OFF_FE  (N_OUT + 1)
#define OFF_ATTN (N_OUT + 2)                       // only 8-byte aligned!
#define N_ATTN  ((size_t)Bb*Hh*Tt*Tt)
#define OFF_DISTS (OFF_ATTN + N_ATTN)

// ---------------- scratch ----------------
__device__ float g_qkv[(size_t)BT * C3];                 // only V region used now
__device__ __nv_bfloat16 g_ah[(size_t)BT * Cc];          // activation hi (x, then o)
__device__ __nv_bfloat16 g_al[(size_t)BT * Cc];
__device__ __nv_bfloat16 g_wh[(size_t)C3 * Cc];
__device__ __nv_bfloat16 g_wl[(size_t)C3 * Cc];
__device__ __nv_bfloat16 g_qh[(size_t)BH * Tt * DH];     // head-major [bh][t][64]
__device__ __nv_bfloat16 g_ql[(size_t)BH * Tt * DH];
__device__ __nv_bfloat16 g_kh[(size_t)BH * Tt * DH];
__device__ __nv_bfloat16 g_kl[(size_t)BH * Tt * DH];

// ---------------- portable helpers (sm_80+) ----------------
__device__ __forceinline__ uint32_t smem_u32(const void* p) {
    uint32_t addr;
    asm("{ .reg .u64 tmp; cvta.to.shared.u64 tmp, %1; cvt.u32.u64 %0, tmp; }"
        : "=r"(addr) : "l"(p));
    return addr;
}
__device__ __forceinline__ void ldsm4(uint32_t r[4], uint32_t addr) {
    asm volatile("ldmatrix.sync.aligned.m8n8.x4.shared.b16 {%0,%1,%2,%3}, [%4];"
        : "=r"(r[0]), "=r"(r[1]), "=r"(r[2]), "=r"(r[3]) : "r"(addr));
}
__device__ __forceinline__ void mma_bf16(float c[4], const uint32_t a[4], const uint32_t b[2]) {
    asm volatile(
        "mma.sync.aligned.m16n8k16.row.col.f32.bf16.bf16.f32 "
        "{%0,%1,%2,%3}, {%4,%5,%6,%7}, {%8,%9}, {%0,%1,%2,%3};"
        : "+f"(c[0]), "+f"(c[1]), "+f"(c[2]), "+f"(c[3])
        : "r"(a[0]), "r"(a[1]), "r"(a[2]), "r"(a[3]), "r"(b[0]), "r"(b[1]));
}
__device__ __forceinline__ void cp_async16(uint32_t saddr, const void* gptr) {
    asm volatile("cp.async.cg.shared.global [%0], [%1], 16;" :: "r"(saddr), "l"(gptr));
}
#define CP_COMMIT() asm volatile("cp.async.commit_group;" ::: "memory")
#define CP_WAIT0()  asm volatile("cp.async.wait_group 0;" ::: "memory")

#define SPAD 40   // smem stride for 32-wide tiles
#define SK   72   // smem stride for 64-wide tiles

// ---------------- kernel: zero energy scalars + write dists (float2) ----------------
__global__ void dists_kernel(float* __restrict__ out) {
    size_t idx2 = (size_t)blockIdx.x * blockDim.x + threadIdx.x;
    if (idx2 < (size_t)Tt * Tt / 2) {
        int i  = (int)(idx2 / (Tt / 2));
        int j  = (int)(idx2 % (Tt / 2)) * 2;
        float2 v;
        v.x = fabsf((float)(i - j));
        v.y = fabsf((float)(i - j - 1));
        *(float2*)&out[OFF_DISTS + (size_t)i * Tt + j] = v;
    }
    if (idx2 == 0) { out[OFF_DE] = 0.f; out[OFF_FE] = 0.f; }
}

// ---------------- kernel: fp32 -> bf16 hi/lo split (float4 vectorized) ----------------
__global__ void cvt_split4(const float* __restrict__ src,
                           __nv_bfloat16* __restrict__ hi,
                           __nv_bfloat16* __restrict__ lo, int n4) {
    int idx = blockIdx.x * blockDim.x + threadIdx.x;
    if (idx >= n4) return;
    float4 v = *(const float4*)&src[idx * 4];
    __nv_bfloat16 h0 = __float2bfloat16(v.x);
    __nv_bfloat16 h1 = __float2bfloat16(v.y);
    __nv_bfloat16 h2 = __float2bfloat16(v.z);
    __nv_bfloat16 h3 = __float2bfloat16(v.w);
    __nv_bfloat162 ha; ha.x = h0; ha.y = h1;
    __nv_bfloat162 hb; hb.x = h2; hb.y = h3;
    __nv_bfloat162 la, lb;
    la.x = __float2bfloat16(v.x - __bfloat162float(h0));
    la.y = __float2bfloat16(v.y - __bfloat162float(h1));
    lb.x = __float2bfloat16(v.z - __bfloat162float(h2));
    lb.y = __float2bfloat16(v.w - __bfloat162float(h3));
    *(__nv_bfloat162*)&hi[idx * 4]     = ha;
    *(__nv_bfloat162*)&hi[idx * 4 + 2] = hb;
    *(__nv_bfloat162*)&lo[idx * 4]     = la;
    *(__nv_bfloat162*)&lo[idx * 4 + 2] = lb;
}

// ---------------- warp-mma GEMM (cp.async double buffered, occ 2) ----------------
// mode 0: fp32 output to Cm (ldc). mode 1: QKV — q/k written split head-major, v fp32.
#define GT_TILE (128 * SPAD)
#define GT_SMEM (2 * 4 * GT_TILE * 2)        // 81920 bytes
__global__ __launch_bounds__(256, 2)
void mma_gemm_tn(const __nv_bfloat16* __restrict__ Ah, const __nv_bfloat16* __restrict__ Al,
                 const __nv_bfloat16* __restrict__ Wh, const __nv_bfloat16* __restrict__ Wl,
                 float* __restrict__ Cm, int K, int lda, int ldw, int ldc, int mode) {
    extern __shared__ __align__(16) __nv_bfloat16 dsmg[];
    int tid  = threadIdx.x;
    int warp = tid >> 5, lane = tid & 31;
    int m0 = blockIdx.y * 128;
    int n0 = blockIdx.x * 128;
    int wm = (warp & 3) * 32;
    int wn = (warp >> 2) * 64;

    const __nv_bfloat16* srcs[4] = { Ah + (size_t)m0 * lda, Al + (size_t)m0 * lda,
                                     Wh + (size_t)n0 * ldw, Wl + (size_t)n0 * ldw };
    int lds[4] = { lda, lda, ldw, ldw };
    uint32_t sb = smem_u32(dsmg);

    float c[16][4];
#pragma unroll
    for (int f = 0; f < 16; f++)
#pragma unroll
        for (int e = 0; e < 4; e++) c[f][e] = 0.f;

    int arow = lane & 15;
    int ablk = (lane >> 4) * 8;
    int nk = K / 32;

#pragma unroll
    for (int t = 0; t < 4; t++) {
        const __nv_bfloat16* s = srcs[t];
        int ld = lds[t];
#pragma unroll
        for (int it = 0; it < 2; it++) {
            int idx = tid + it * 256;
            int row = idx >> 2;
            int cc  = idx & 3;
            cp_async16(sb + (t * GT_TILE + row * SPAD + cc * 8) * 2,
                       s + (size_t)row * ld + cc * 8);
        }
    }
    CP_COMMIT();

    for (int kc = 0; kc < nk; kc++) {
        CP_WAIT0();
        __syncthreads();
        if (kc + 1 < nk) {
            int nb = (kc + 1) & 1;
            int k0 = (kc + 1) * 32;
#pragma unroll
            for (int t = 0; t < 4; t++) {
                const __nv_bfloat16* s = srcs[t] + k0;
                int ld = lds[t];
#pragma unroll
                for (int it = 0; it < 2; it++) {
                    int idx = tid + it * 256;
                    int row = idx >> 2;
                    int cc  = idx & 3;
                    cp_async16(sb + ((nb * 4 + t) * GT_TILE + row * SPAD + cc * 8) * 2,
                               s + (size_t)row * ld + cc * 8);
                }
            }
            CP_COMMIT();
        }
        uint32_t bo = (uint32_t)((kc & 1) * 4 * GT_TILE) * 2;

#pragma unroll
        for (int ks = 0; ks < 32; ks += 16) {
            uint32_t a_hi[2][4], a_lo[2][4];
#pragma unroll
            for (int mf = 0; mf < 2; mf++) {
                uint32_t off = ((wm + mf * 16 + arow) * SPAD + ks + ablk) * 2;
                ldsm4(a_hi[mf], sb + bo + 0 * GT_TILE * 2 + off);
                ldsm4(a_lo[mf], sb + bo + 1 * GT_TILE * 2 + off);
            }
            uint32_t b_hi[8][2], b_lo[8][2];
#pragma unroll
            for (int pr = 0; pr < 4; pr++) {
                uint32_t off = ((wn + pr * 16 + arow) * SPAD + ks + ablk) * 2;
                uint32_t t4[4];
                ldsm4(t4, sb + bo + 2 * GT_TILE * 2 + off);
                b_hi[pr*2+0][0] = t4[0]; b_hi[pr*2+0][1] = t4[2];
                b_hi[pr*2+1][0] = t4[1]; b_hi[pr*2+1][1] = t4[3];
                ldsm4(t4, sb + bo + 3 * GT_TILE * 2 + off);
                b_lo[pr*2+0][0] = t4[0]; b_lo[pr*2+0][1] = t4[2];
                b_lo[pr*2+1][0] = t4[1]; b_lo[pr*2+1][1] = t4[3];
            }
#pragma unroll
            for (int mf = 0; mf < 2; mf++)
#pragma unroll
                for (int nf = 0; nf < 8; nf++) {
                    mma_bf16(c[mf*8+nf], a_hi[mf], b_hi[nf]);
                    mma_bf16(c[mf*8+nf], a_hi[mf], b_lo[nf]);
                    mma_bf16(c[mf*8+nf], a_lo[mf], b_hi[nf]);
                }
        }
    }

    int r = lane >> 2, q2 = (lane & 3) * 2;
    if (mode == 0 || n0 >= 2048) {
#pragma unroll
        for (int mf = 0; mf < 2; mf++)
#pragma unroll
            for (int nf = 0; nf < 8; nf++) {
                int m = m0 + wm + mf * 16 + r;
                int n = n0 + wn + nf * 8 + q2;
                float* f = c[mf*8+nf];
                *(float2*)&Cm[(size_t)m * ldc + n]       = make_float2(f[0], f[1]);
                *(float2*)&Cm[(size_t)(m + 8) * ldc + n] = make_float2(f[2], f[3]);
            }
    } else {
        __nv_bfloat16* Hd = (n0 < 1024) ? g_qh : g_kh;
        __nv_bfloat16* Ld = (n0 < 1024) ? g_ql : g_kl;
#pragma unroll
        for (int mf = 0; mf < 2; mf++)
#pragma unroll
            for (int nf = 0; nf < 8; nf++) {
                int m = m0 + wm + mf * 16 + r;
                int n = n0 + wn + nf * 8 + q2;
                int nin = n & 1023;
                int h = nin >> 6, d = nin & 63;
                float* f = c[mf*8+nf];
#pragma unroll
                for (int rr = 0; rr < 2; rr++) {
                    int mm = m + rr * 8;
                    int b = mm >> 11, t = mm & 2047;
                    size_t dst = (((size_t)(b * Hh + h) * Tt) + t) * DH + d;
                    float v0 = f[rr*2+0], v1 = f[rr*2+1];
                    __nv_bfloat16 h0 = __float2bfloat16(v0);
                    __nv_bfloat16 h1 = __float2bfloat16(v1);
                    __nv_bfloat162 hv; hv.x = h0; hv.y = h1;
                    __nv_bfloat162 lv;
                    lv.x = __float2bfloat16(v0 - __bfloat162float(h0));
                    lv.y = __float2bfloat16(v1 - __bfloat162float(h1));
                    *(__nv_bfloat162*)&Hd[dst] = hv;
                    *(__nv_bfloat162*)&Ld[dst] = lv;
                }
            }
    }
}

// ---------------- fused logits+softmax helpers ----------------
// S tile (128x128) = Q K^T via split bf16, K-dim 64. No syncs inside.
__device__ __forceinline__ void compute_S(uint32_t sQh, uint32_t sQl,
                                          uint32_t sKh, uint32_t sKl,
                                          int wm, int wn, int lane, float (*c)[4]) {
#pragma unroll
    for (int f = 0; f < 16; f++)
#pragma unroll
        for (int e = 0; e < 4; e++) c[f][e] = 0.f;
    int arw = lane & 15, ablk = (lane >> 4) * 8;
#pragma unroll
    for (int ks = 0; ks < 64; ks += 16) {
        uint32_t a_hi[2][4], a_lo[2][4];
#pragma unroll
        for (int mf = 0; mf < 2; mf++) {
            uint32_t off = (uint32_t)((wm + mf * 16 + arw) * SK + ks + ablk) * 2;
            ldsm4(a_hi[mf], sQh + off);
            ldsm4(a_lo[mf], sQl + off);
        }
        uint32_t b_hi[8][2], b_lo[8][2];
#pragma unroll
        for (int pr = 0; pr < 4; pr++) {
            uint32_t off = (uint32_t)((wn + pr * 16 + arw) * SK + ks + ablk) * 2;
            uint32_t t4[4];
            ldsm4(t4, sKh + off);
            b_hi[pr*2+0][0] = t4[0]; b_hi[pr*2+0][1] = t4[2];
            b_hi[pr*2+1][0] = t4[1]; b_hi[pr*2+1][1] = t4[3];
            ldsm4(t4, sKl + off);
            b_lo[pr*2+0][0] = t4[0]; b_lo[pr*2+0][1] = t4[2];
            b_lo[pr*2+1][0] = t4[1]; b_lo[pr*2+1][1] = t4[3];
        }
#pragma unroll
        for (int mf = 0; mf < 2; mf++)
#pragma unroll
            for (int nf = 0; nf < 8; nf++) {
                mma_bf16(c[mf*8+nf], a_hi[mf], b_hi[nf]);
                mma_bf16(c[mf*8+nf], a_hi[mf], b_lo[nf]);
                mma_bf16(c[mf*8+nf], a_lo[mf], b_hi[nf]);
            }
    }
}

// issue cp.async for a 128x64 bf16 tile into smem (stride SK)
__device__ __forceinline__ void load_tile64(uint32_t sdst, const __nv_bfloat16* __restrict__ g,
                                            int tid) {
#pragma unroll
    for (int it = 0; it < 4; it++) {
        int idx = tid + it * 256;
        int row = idx >> 3, cc = idx & 7;
        cp_async16(sdst + (uint32_t)(row * SK + cc * 8) * 2, g + (size_t)row * DH + cc * 8);
    }
}

// fused smem layout (bytes)
#define FS_QH 0
#define FS_QL 18432
#define FS_KH 36864
#define FS_KL 55296
#define FS_TSTAT 73728   // float[2][128]
#define FS_TMAX  74752   // float[128]
#define FS_RM    75264   // float[128]
#define FS_RS    75776   // float[128]
#define FS_ERED  76288   // float[16]
#define FS_SMEM  76352

// ---------------- fused logits + softmax + attn write + energies ----------------
__global__ __launch_bounds__(256, 2)
void sm_fused(const float* __restrict__ dscales, float* __restrict__ d_out) {
    extern __shared__ __align__(16) char dsm[];
    float* tstat = (float*)(dsm + FS_TSTAT);
    float* tmaxA = (float*)(dsm + FS_TMAX);
    float* rmA   = (float*)(dsm + FS_RM);
    float* rsA   = (float*)(dsm + FS_RS);
    float* ered  = (float*)(dsm + FS_ERED);

    int tid  = threadIdx.x;
    int warp = tid >> 5, lane = tid & 31;
    int wm = (warp & 3) * 32;
    int wn = (warp >> 2) * 64;
    int wnIdx = warp >> 2;
    int it = 15 - blockIdx.x;               // big tiles first
    int bh = blockIdx.y;
    int h = bh & 15;
    int i0 = it * 128;
    float ds = dscales[h];

    uint32_t sB = smem_u32(dsm);
    uint32_t uQh = sB + FS_QH, uQl = sB + FS_QL;
    uint32_t uKh = sB + FS_KH, uKl = sB + FS_KL;

    size_t qoff = ((size_t)bh * Tt + i0) * DH;
    load_tile64(uQh, g_qh + qoff, tid);
    load_tile64(uQl, g_ql + qoff, tid);
    CP_COMMIT();
    if (tid < 128) { rmA[tid] = -INFINITY; rsA[tid] = 0.f; }

    int r = lane >> 2, q2 = (lane & 3) * 2;
    float c[16][4];

    // ============ pass 1: row max / running sum ============
    for (int jt = 0; jt <= it; jt++) {
        int j0 = jt * 128;
        size_t koff = ((size_t)bh * Tt + j0) * DH;
        load_tile64(uKh, g_kh + koff, tid);
        load_tile64(uKl, g_kl + koff, tid);
        CP_COMMIT();
        CP_WAIT0();
        __syncthreads();
        compute_S(uQh, uQl, uKh, uKl, wm, wn, lane, c);
        // transform in place (+ causal mask)
#pragma unroll
        for (int mf = 0; mf < 2; mf++) {
            int ri0 = i0 + wm + mf * 16 + r;
#pragma unroll
            for (int nf = 0; nf < 8; nf++) {
                int j = j0 + wn + nf * 8 + q2;
                float* f = c[mf*8+nf];
                f[0] = (j     <= ri0    ) ? f[0]*0.125f - ds*(float)(ri0 - j)       : -INFINITY;
                f[1] = (j + 1 <= ri0    ) ? f[1]*0.125f - ds*(float)(ri0 - j - 1)   : -INFINITY;
                f[2] = (j     <= ri0 + 8) ? f[2]*0.125f - ds*(float)(ri0 + 8 - j)   : -INFINITY;
                f[3] = (j + 1 <= ri0 + 8) ? f[3]*0.125f - ds*(float)(ri0 + 8 - j-1) : -INFINITY;
            }
        }
        // tile row maxes
        float tmx[4] = {-INFINITY, -INFINITY, -INFINITY, -INFINITY};
#pragma unroll
        for (int mf = 0; mf < 2; mf++)
#pragma unroll
            for (int nf = 0; nf < 8; nf++) {
                float* f = c[mf*8+nf];
                tmx[mf*2+0] = fmaxf(tmx[mf*2+0], fmaxf(f[0], f[1]));
                tmx[mf*2+1] = fmaxf(tmx[mf*2+1], fmaxf(f[2], f[3]));
            }
#pragma unroll
        for (int off = 1; off <= 2; off <<= 1)
#pragma unroll
            for (int k = 0; k < 4; k++)
                tmx[k] = fmaxf(tmx[k], __shfl_xor_sync(0xFFFFFFFFu, tmx[k], off));
        if ((lane & 3) == 0) {
#pragma unroll
            for (int k = 0; k < 4; k++)
                tstat[wnIdx * 128 + wm + (k >> 1) * 16 + (k & 1) * 8 + r] = tmx[k];
        }
        __syncthreads();
        if (tid < 128) tmaxA[tid] = fmaxf(tstat[tid], tstat[128 + tid]);
        __syncthreads();
        // tile exp sums
        float tsm[4] = {0.f, 0.f, 0.f, 0.f};
#pragma unroll
        for (int mf = 0; mf < 2; mf++) {
            float m0 = tmaxA[wm + mf * 16 + r];
            float m1 = tmaxA[wm + mf * 16 + 8 + r];
#pragma unroll
            for (int nf = 0; nf < 8; nf++) {
                float* f = c[mf*8+nf];
                tsm[mf*2+0] += __expf(f[0] - m0) + __expf(f[1] - m0);
                tsm[mf*2+1] += __expf(f[2] - m1) + __expf(f[3] - m1);
            }
        }
#pragma unroll
        for (int off = 1; off <= 2; off <<= 1)
#pragma unroll
            for (int k = 0; k < 4; k++)
                tsm[k] += __shfl_xor_sync(0xFFFFFFFFu, tsm[k], off);
        if ((lane & 3) == 0) {
#pragma unroll
            for (int k = 0; k < 4; k++)
                tstat[wnIdx * 128 + wm + (k >> 1) * 16 + (k & 1) * 8 + r] = tsm[k];
        }
        __syncthreads();
        if (tid < 128) {
            float ts = tstat[tid] + tstat[128 + tid];
            float tm = tmaxA[tid];
            float mo = rmA[tid];
            float mn = fmaxf(mo, tm);
            rsA[tid] = rsA[tid] * __expf(mo - mn) + ts * __expf(tm - mn);
            rmA[tid] = mn;
        }
        __syncthreads();
    }
    if (tid < 128) rsA[tid] = 1.f / rsA[tid];
    __syncthreads();

    // ============ pass 2: write normalized attn + energies ============
    float de = 0.f, fe = 0.f;
    size_t abase = OFF_ATTN + (size_t)bh * Tt * Tt;

    for (int jt = 0; jt <= it; jt++) {
        int j0 = jt * 128;
        size_t koff = ((size_t)bh * Tt + j0) * DH;
        load_tile64(uKh, g_kh + koff, tid);
        load_tile64(uKl, g_kl + koff, tid);
        CP_COMMIT();
        CP_WAIT0();
        __syncthreads();
        compute_S(uQh, uQl, uKh, uKl, wm, wn, lane, c);

#pragma unroll
        for (int mf = 0; mf < 2; mf++) {
            int row0 = wm + mf * 16 + r;
            int ri0 = i0 + row0;
            float m0 = rmA[row0],     iv0 = rsA[row0];
            float m1 = rmA[row0 + 8], iv1 = rsA[row0 + 8];
#pragma unroll
            for (int nf = 0; nf < 8; nf++) {
                int j = j0 + wn + nf * 8 + q2;
                float* f = c[mf*8+nf];
                float a0 = (j     <= ri0    ) ? __expf(f[0]*0.125f - ds*(float)(ri0-j)     - m0) * iv0 : 0.f;
                float a1 = (j + 1 <= ri0    ) ? __expf(f[1]*0.125f - ds*(float)(ri0-j-1)   - m0) * iv0 : 0.f;
                float a2 = (j     <= ri0 + 8) ? __expf(f[2]*0.125f - ds*(float)(ri0+8-j)   - m1) * iv1 : 0.f;
                float a3 = (j + 1 <= ri0 + 8) ? __expf(f[3]*0.125f - ds*(float)(ri0+8-j-1) - m1) * iv1 : 0.f;
                *(float2*)&d_out[abase + (size_t)ri0 * Tt + j]       = make_float2(a0, a1);
                *(float2*)&d_out[abase + (size_t)(ri0 + 8) * Tt + j] = make_float2(a2, a3);
                de += a0*(float)(ri0-j) + a1*(float)(ri0-j-1) + a2*(float)(ri0+8-j) + a3*(float)(ri0+8-j-1);
                fe -= a0*__logf(a0+1e-9f) + a1*__logf(a1+1e-9f) + a2*__logf(a2+1e-9f) + a3*__logf(a3+1e-9f);
            }
        }
        __syncthreads();     // all ldsm on sK done before next jt load
    }

    // zero-fill the upper attn region (cols beyond (it+1)*128)
    int w2 = (15 - it) * 64;     // float2s per row
    for (int row = 0; row < 128; row++) {
        size_t base = abase + (size_t)(i0 + row) * Tt + (it + 1) * 128;
        for (int c2 = tid; c2 < w2; c2 += 256)
            *(float2*)&d_out[base + c2 * 2] = make_float2(0.f, 0.f);
    }

    // energies
#pragma unroll
    for (int off = 16; off > 0; off >>= 1) {
        de += __shfl_xor_sync(0xFFFFFFFFu, de, off);
        fe += __shfl_xor_sync(0xFFFFFFFFu, fe, off);
    }
    if (lane == 0) { ered[warp] = de; ered[8 + warp] = fe; }
    __syncthreads();
    if (tid == 0) {
        float sde = 0.f, sfe = 0.f;
#pragma unroll
        for (int w = 0; w < 8; w++) { sde += ered[w]; sfe += ered[8 + w]; }
        atomicAdd(&d_out[OFF_DE], sde * (1.f / 65536.f));
        atomicAdd(&d_out[OFF_FE], sfe * (1.f / 65536.f));
    }
}

// ---------------- PV via warp-mma (occ 2): writes o split bf16 hi/lo ----------------
__global__ __launch_bounds__(256, 2) void pv_mma(const float* __restrict__ d_out_c) {
    __shared__ __align__(16) __nv_bfloat16 sAh[128 * SPAD];
    __shared__ __align__(16) __nv_bfloat16 sAl[128 * SPAD];
    __shared__ __align__(16) __nv_bfloat16 sVh[64 * SPAD];
    __shared__ __align__(16) __nv_bfloat16 sVl[64 * SPAD];
    int it = blockIdx.x;
    int bh = blockIdx.y;
    int b = bh >> 4, h = bh & 15;
    int i0 = it * 128;
    int tid  = threadIdx.x;
    int warp = tid >> 5, lane = tid & 31;
    int wm = (warp & 3) * 32;
    int wn = (warp >> 2) * 32;

    const float* Arow = d_out_c + OFF_ATTN + (size_t)bh * Tt * Tt;
    const float* Vb = g_qkv + (size_t)(b * Tt) * C3 + 2 * Cc + h * DH;

    uint32_t sbAh = smem_u32(sAh), sbAl = smem_u32(sAl);
    uint32_t sbVh = smem_u32(sVh), sbVl = smem_u32(sVl);

    float c[8][4];
#pragma unroll
    for (int f = 0; f < 8; f++)
#pragma unroll
        for (int e = 0; e < 4; e++) c[f][e] = 0.f;

    int arw = lane & 15;
    int ablk = (lane >> 4) * 8;
    int kmax = i0 + 128;

    for (int k0 = 0; k0 < kmax; k0 += 32) {
#pragma unroll
        for (int t = 0; t < 8; t++) {
            int idx = tid + t * 256;
            int row = idx >> 4;
            int cc  = idx & 15;
            float2 s = *(const float2*)&Arow[(size_t)(i0 + row) * Tt + k0 + cc * 2];
            __nv_bfloat16 h0 = __float2bfloat16(s.x);
            __nv_bfloat16 h1 = __float2bfloat16(s.y);
            sAh[row * SPAD + cc*2]     = h0;
            sAh[row * SPAD + cc*2 + 1] = h1;
            sAl[row * SPAD + cc*2]     = __float2bfloat16(s.x - __bfloat162float(h0));
            sAl[row * SPAD + cc*2 + 1] = __float2bfloat16(s.y - __bfloat162float(h1));
        }
#pragma unroll
        for (int t = 0; t < 8; t++) {
            int idx = tid + t * 256;
            int kk = idx >> 6;
            int d  = idx & 63;
            float xv = Vb[(size_t)(k0 + kk) * C3 + d];
            __nv_bfloat16 hh = __float2bfloat16(xv);
            sVh[d * SPAD + kk] = hh;
            sVl[d * SPAD + kk] = __float2bfloat16(xv - __bfloat162float(hh));
        }
        __syncthreads();

#pragma unroll
        for (int ks = 0; ks < 32; ks += 16) {
            uint32_t a_hi[2][4], a_lo[2][4];
#pragma unroll
            for (int mf = 0; mf < 2; mf++) {
                uint32_t off = ((wm + mf * 16 + arw) * SPAD + ks + ablk) * 2;
                ldsm4(a_hi[mf], sbAh + off);
                ldsm4(a_lo[mf], sbAl + off);
            }
            uint32_t b_hi[4][2], b_lo[4][2];
#pragma unroll
            for (int pr = 0; pr < 2; pr++) {
                uint32_t off = ((wn + pr * 16 + arw) * SPAD + ks + ablk) * 2;
                uint32_t t4[4];
                ldsm4(t4, sbVh + off);
                b_hi[pr*2+0][0] = t4[0]; b_hi[pr*2+0][1] = t4[2];
                b_hi[pr*2+1][0] = t4[1]; b_hi[pr*2+1][1] = t4[3];
                ldsm4(t4, sbVl + off);
                b_lo[pr*2+0][0] = t4[0]; b_lo[pr*2+0][1] = t4[2];
                b_lo[pr*2+1][0] = t4[1]; b_lo[pr*2+1][1] = t4[3];
            }
#pragma unroll
            for (int mf = 0; mf < 2; mf++)
#pragma unroll
                for (int nf = 0; nf < 4; nf++) {
                    mma_bf16(c[mf*4+nf], a_hi[mf], b_hi[nf]);
                    mma_bf16(c[mf*4+nf], a_hi[mf], b_lo[nf]);
                    mma_bf16(c[mf*4+nf], a_lo[mf], b_hi[nf]);
                }
        }
        __syncthreads();
    }

    int r = lane >> 2, q2 = (lane & 3) * 2;
#pragma unroll
    for (int mf = 0; mf < 2; mf++)
#pragma unroll
        for (int nf = 0; nf < 4; nf++) {
            int n = wn + nf * 8 + q2;
            float* f = c[mf*4+nf];
#pragma unroll
            for (int rr = 0; rr < 2; rr++) {
                int m = i0 + wm + mf * 16 + r + rr * 8;
                size_t dst = (size_t)(b * Tt + m) * Cc + h * DH + n;
                float v0 = f[rr*2+0], v1 = f[rr*2+1];
                __nv_bfloat16 h0 = __float2bfloat16(v0);
                __nv_bfloat16 h1 = __float2bfloat16(v1);
                __nv_bfloat162 hv; hv.x = h0; hv.y = h1;
                __nv_bfloat162 lv;
                lv.x = __float2bfloat16(v0 - __bfloat162float(h0));
                lv.y = __float2bfloat16(v1 - __bfloat162float(h1));
                *(__nv_bfloat162*)&g_ah[dst] = hv;
                *(__nv_bfloat162*)&g_al[dst] = lv;
            }
        }
}

// ---------------- launch ----------------
extern "C" void kernel_launch(void* const* d_in, const int* in_sizes, int n_in,
                              void* d_out, int out_size) {
    const float* x       = (const float*)d_in[0];
    const float* qkv_w   = (const float*)d_in[1];
    const float* proj_w  = (const float*)d_in[2];
    const float* dscales = (const float*)d_in[3];
    float* out = (float*)d_out;

    float *p_qkv;
    __nv_bfloat16 *p_ah, *p_al, *p_wh, *p_wl;
    cudaGetSymbolAddress((void**)&p_qkv, g_qkv);
    cudaGetSymbolAddress((void**)&p_ah,  g_ah);
    cudaGetSymbolAddress((void**)&p_al,  g_al);
    cudaGetSymbolAddress((void**)&p_wh,  g_wh);
    cudaGetSymbolAddress((void**)&p_wl,  g_wl);

    cudaFuncSetAttribute(mma_gemm_tn, cudaFuncAttributeMaxDynamicSharedMemorySize, GT_SMEM);
    cudaFuncSetAttribute(sm_fused,    cudaFuncAttributeMaxDynamicSharedMemorySize, FS_SMEM);

    // 1. dists + zero scalars (float2)
    dists_kernel<<<(unsigned)(((size_t)Tt * Tt / 2 + 255) / 256), 256>>>(out);

    // 2. split x and qkv_w to bf16 hi/lo (vectorized)
    cvt_split4<<<(BT * Cc / 4 + 255) / 256, 256>>>(x, p_ah, p_al, BT * Cc / 4);
    cvt_split4<<<(C3 * Cc / 4 + 255) / 256, 256>>>(qkv_w, p_wh, p_wl, C3 * Cc / 4);

    // 3. QKV GEMM (128x128, occ 2; mode 1: q/k split head-major, v fp32)
    {
        dim3 grid(C3 / 128, BT / 128);
        mma_gemm_tn<<<grid, 256, GT_SMEM>>>(p_ah, p_al, p_wh, p_wl, p_qkv, Cc, Cc, Cc, C3, 1);
    }

    // 4. fused logits + softmax + attn write + energies
    {
        dim3 grid(Tt / 128, BH);
        sm_fused<<<grid, 256, FS_SMEM>>>(dscales, out);
    }

    // 5. PV -> o split bf16 directly into g_ah/g_al
    {
        dim3 grid(Tt / 128, BH);
        pv_mma<<<grid, 256>>>(out);
    }

    // 6. split proj_w, then proj GEMM (mode 0) -> out[0..N_OUT)
    cvt_split4<<<(Cc * Cc / 4 + 255) / 256, 256>>>(proj_w, p_wh, p_wl, Cc * Cc / 4);
    {
        dim3 grid(Cc / 128, BT / 128);
        mma_gemm_tn<<<grid, 256, GT_SMEM>>>(p_ah, p_al, p_wh, p_wl, out, Cc, Cc, Cc, Cc, 0);
    }
}

// round 13
// speedup vs baseline: 1.0839x; 1.0839x over previous
#include <cuda_runtime.h>
#include <cuda_bf16.h>
#include <math.h>
#include <stdint.h>

// ---------------- problem constants ----------------
#define Bb 2
#define Tt 2048
#define Cc 1024
#define Hh 16
#define DH 64
#define BT (Bb*Tt)            // 4096
#define C3 (3*Cc)             // 3072
#define BH (Bb*Hh)            // 32

// output buffer layout (flatten-concat of the reference tuple, fp32)
#define N_OUT   ((size_t)Bb*Tt*Cc)                 // 4,194,304
#define OFF_DE  (N_OUT)
#define OFF_FE  (N_OUT + 1)
#define OFF_ATTN (N_OUT + 2)                       // only 8-byte aligned!
#define N_ATTN  ((size_t)Bb*Hh*Tt*Tt)
#define OFF_DISTS (OFF_ATTN + N_ATTN)

// ---------------- scratch ----------------
__device__ float g_qkv[(size_t)BT * C3];                 // only V region used now
__device__ __nv_bfloat16 g_ah[(size_t)BT * Cc];          // activation hi (x, then o)
__device__ __nv_bfloat16 g_al[(size_t)BT * Cc];
__device__ __nv_bfloat16 g_wh[(size_t)C3 * Cc];
__device__ __nv_bfloat16 g_wl[(size_t)C3 * Cc];
__device__ __nv_bfloat16 g_qh[(size_t)BH * Tt * DH];     // head-major [bh][t][64]
__device__ __nv_bfloat16 g_ql[(size_t)BH * Tt * DH];
__device__ __nv_bfloat16 g_kh[(size_t)BH * Tt * DH];
__device__ __nv_bfloat16 g_kl[(size_t)BH * Tt * DH];

// ---------------- portable helpers (sm_80+) ----------------
__device__ __forceinline__ uint32_t smem_u32(const void* p) {
    uint32_t addr;
    asm("{ .reg .u64 tmp; cvta.to.shared.u64 tmp, %1; cvt.u32.u64 %0, tmp; }"
        : "=r"(addr) : "l"(p));
    return addr;
}
__device__ __forceinline__ void ldsm4(uint32_t r[4], uint32_t addr) {
    asm volatile("ldmatrix.sync.aligned.m8n8.x4.shared.b16 {%0,%1,%2,%3}, [%4];"
        : "=r"(r[0]), "=r"(r[1]), "=r"(r[2]), "=r"(r[3]) : "r"(addr));
}
__device__ __forceinline__ void mma_bf16(float c[4], const uint32_t a[4], const uint32_t b[2]) {
    asm volatile(
        "mma.sync.aligned.m16n8k16.row.col.f32.bf16.bf16.f32 "
        "{%0,%1,%2,%3}, {%4,%5,%6,%7}, {%8,%9}, {%0,%1,%2,%3};"
        : "+f"(c[0]), "+f"(c[1]), "+f"(c[2]), "+f"(c[3])
        : "r"(a[0]), "r"(a[1]), "r"(a[2]), "r"(a[3]), "r"(b[0]), "r"(b[1]));
}
__device__ __forceinline__ void cp_async16(uint32_t saddr, const void* gptr) {
    asm volatile("cp.async.cg.shared.global [%0], [%1], 16;" :: "r"(saddr), "l"(gptr));
}
#define CP_COMMIT() asm volatile("cp.async.commit_group;" ::: "memory")
#define CP_WAIT0()  asm volatile("cp.async.wait_group 0;" ::: "memory")

#define SPAD 40   // smem stride for 32-wide tiles
#define SK   72   // smem stride for 64-wide tiles

// ---------------- kernel: zero energy scalars + write dists (float2) ----------------
__global__ void dists_kernel(float* __restrict__ out) {
    size_t idx2 = (size_t)blockIdx.x * blockDim.x + threadIdx.x;
    if (idx2 < (size_t)Tt * Tt / 2) {
        int i  = (int)(idx2 / (Tt / 2));
        int j  = (int)(idx2 % (Tt / 2)) * 2;
        float2 v;
        v.x = fabsf((float)(i - j));
        v.y = fabsf((float)(i - j - 1));
        *(float2*)&out[OFF_DISTS + (size_t)i * Tt + j] = v;
    }
    if (idx2 == 0) { out[OFF_DE] = 0.f; out[OFF_FE] = 0.f; }
}

// ---------------- kernel: fp32 -> bf16 hi/lo split (float4 vectorized) ----------------
__global__ void cvt_split4(const float* __restrict__ src,
                           __nv_bfloat16* __restrict__ hi,
                           __nv_bfloat16* __restrict__ lo, int n4) {
    int idx = blockIdx.x * blockDim.x + threadIdx.x;
    if (idx >= n4) return;
    float4 v = *(const float4*)&src[idx * 4];
    __nv_bfloat16 h0 = __float2bfloat16(v.x);
    __nv_bfloat16 h1 = __float2bfloat16(v.y);
    __nv_bfloat16 h2 = __float2bfloat16(v.z);
    __nv_bfloat16 h3 = __float2bfloat16(v.w);
    __nv_bfloat162 ha; ha.x = h0; ha.y = h1;
    __nv_bfloat162 hb; hb.x = h2; hb.y = h3;
    __nv_bfloat162 la, lb;
    la.x = __float2bfloat16(v.x - __bfloat162float(h0));
    la.y = __float2bfloat16(v.y - __bfloat162float(h1));
    lb.x = __float2bfloat16(v.z - __bfloat162float(h2));
    lb.y = __float2bfloat16(v.w - __bfloat162float(h3));
    *(__nv_bfloat162*)&hi[idx * 4]     = ha;
    *(__nv_bfloat162*)&hi[idx * 4 + 2] = hb;
    *(__nv_bfloat162*)&lo[idx * 4]     = la;
    *(__nv_bfloat162*)&lo[idx * 4 + 2] = lb;
}

// ---------------- warp-mma GEMM (cp.async double buffered, occ 2) ----------------
// mode 0: fp32 output to Cm (ldc). mode 1: QKV — q/k written split head-major, v fp32.
#define GT_TILE (128 * SPAD)
#define GT_SMEM (2 * 4 * GT_TILE * 2)        // 81920 bytes
__global__ __launch_bounds__(256, 2)
void mma_gemm_tn(const __nv_bfloat16* __restrict__ Ah, const __nv_bfloat16* __restrict__ Al,
                 const __nv_bfloat16* __restrict__ Wh, const __nv_bfloat16* __restrict__ Wl,
                 float* __restrict__ Cm, int K, int lda, int ldw, int ldc, int mode) {
    extern __shared__ __align__(16) __nv_bfloat16 dsmg[];
    int tid  = threadIdx.x;
    int warp = tid >> 5, lane = tid & 31;
    int m0 = blockIdx.y * 128;
    int n0 = blockIdx.x * 128;
    int wm = (warp & 3) * 32;
    int wn = (warp >> 2) * 64;

    const __nv_bfloat16* srcs[4] = { Ah + (size_t)m0 * lda, Al + (size_t)m0 * lda,
                                     Wh + (size_t)n0 * ldw, Wl + (size_t)n0 * ldw };
    int lds[4] = { lda, lda, ldw, ldw };
    uint32_t sb = smem_u32(dsmg);

    float c[16][4];
#pragma unroll
    for (int f = 0; f < 16; f++)
#pragma unroll
        for (int e = 0; e < 4; e++) c[f][e] = 0.f;

    int arow = lane & 15;
    int ablk = (lane >> 4) * 8;
    int nk = K / 32;

#pragma unroll
    for (int t = 0; t < 4; t++) {
        const __nv_bfloat16* s = srcs[t];
        int ld = lds[t];
#pragma unroll
        for (int it = 0; it < 2; it++) {
            int idx = tid + it * 256;
            int row = idx >> 2;
            int cc  = idx & 3;
            cp_async16(sb + (t * GT_TILE + row * SPAD + cc * 8) * 2,
                       s + (size_t)row * ld + cc * 8);
        }
    }
    CP_COMMIT();

    for (int kc = 0; kc < nk; kc++) {
        CP_WAIT0();
        __syncthreads();
        if (kc + 1 < nk) {
            int nb = (kc + 1) & 1;
            int k0 = (kc + 1) * 32;
#pragma unroll
            for (int t = 0; t < 4; t++) {
                const __nv_bfloat16* s = srcs[t] + k0;
                int ld = lds[t];
#pragma unroll
                for (int it = 0; it < 2; it++) {
                    int idx = tid + it * 256;
                    int row = idx >> 2;
                    int cc  = idx & 3;
                    cp_async16(sb + ((nb * 4 + t) * GT_TILE + row * SPAD + cc * 8) * 2,
                               s + (size_t)row * ld + cc * 8);
                }
            }
            CP_COMMIT();
        }
        uint32_t bo = (uint32_t)((kc & 1) * 4 * GT_TILE) * 2;

#pragma unroll
        for (int ks = 0; ks < 32; ks += 16) {
            uint32_t a_hi[2][4], a_lo[2][4];
#pragma unroll
            for (int mf = 0; mf < 2; mf++) {
                uint32_t off = ((wm + mf * 16 + arow) * SPAD + ks + ablk) * 2;
                ldsm4(a_hi[mf], sb + bo + 0 * GT_TILE * 2 + off);
                ldsm4(a_lo[mf], sb + bo + 1 * GT_TILE * 2 + off);
            }
            uint32_t b_hi[8][2], b_lo[8][2];
#pragma unroll
            for (int pr = 0; pr < 4; pr++) {
                uint32_t off = ((wn + pr * 16 + arow) * SPAD + ks + ablk) * 2;
                uint32_t t4[4];
                ldsm4(t4, sb + bo + 2 * GT_TILE * 2 + off);
                b_hi[pr*2+0][0] = t4[0]; b_hi[pr*2+0][1] = t4[2];
                b_hi[pr*2+1][0] = t4[1]; b_hi[pr*2+1][1] = t4[3];
                ldsm4(t4, sb + bo + 3 * GT_TILE * 2 + off);
                b_lo[pr*2+0][0] = t4[0]; b_lo[pr*2+0][1] = t4[2];
                b_lo[pr*2+1][0] = t4[1]; b_lo[pr*2+1][1] = t4[3];
            }
#pragma unroll
            for (int mf = 0; mf < 2; mf++)
#pragma unroll
                for (int nf = 0; nf < 8; nf++) {
                    mma_bf16(c[mf*8+nf], a_hi[mf], b_hi[nf]);
                    mma_bf16(c[mf*8+nf], a_hi[mf], b_lo[nf]);
                    mma_bf16(c[mf*8+nf], a_lo[mf], b_hi[nf]);
                }
        }
    }

    int r = lane >> 2, q2 = (lane & 3) * 2;
    if (mode == 0 || n0 >= 2048) {
#pragma unroll
        for (int mf = 0; mf < 2; mf++)
#pragma unroll
            for (int nf = 0; nf < 8; nf++) {
                int m = m0 + wm + mf * 16 + r;
                int n = n0 + wn + nf * 8 + q2;
                float* f = c[mf*8+nf];
                *(float2*)&Cm[(size_t)m * ldc + n]       = make_float2(f[0], f[1]);
                *(float2*)&Cm[(size_t)(m + 8) * ldc + n] = make_float2(f[2], f[3]);
            }
    } else {
        __nv_bfloat16* Hd = (n0 < 1024) ? g_qh : g_kh;
        __nv_bfloat16* Ld = (n0 < 1024) ? g_ql : g_kl;
#pragma unroll
        for (int mf = 0; mf < 2; mf++)
#pragma unroll
            for (int nf = 0; nf < 8; nf++) {
                int m = m0 + wm + mf * 16 + r;
                int n = n0 + wn + nf * 8 + q2;
                int nin = n & 1023;
                int h = nin >> 6, d = nin & 63;
                float* f = c[mf*8+nf];
#pragma unroll
                for (int rr = 0; rr < 2; rr++) {
                    int mm = m + rr * 8;
                    int b = mm >> 11, t = mm & 2047;
                    size_t dst = (((size_t)(b * Hh + h) * Tt) + t) * DH + d;
                    float v0 = f[rr*2+0], v1 = f[rr*2+1];
                    __nv_bfloat16 h0 = __float2bfloat16(v0);
                    __nv_bfloat16 h1 = __float2bfloat16(v1);
                    __nv_bfloat162 hv; hv.x = h0; hv.y = h1;
                    __nv_bfloat162 lv;
                    lv.x = __float2bfloat16(v0 - __bfloat162float(h0));
                    lv.y = __float2bfloat16(v1 - __bfloat162float(h1));
                    *(__nv_bfloat162*)&Hd[dst] = hv;
                    *(__nv_bfloat162*)&Ld[dst] = lv;
                }
            }
    }
}

// ---------------- warp-mma logits (triangular grid, single load phase, occ 2) ---------
#define LT_TILE (128 * SK)                  // elems per 64-wide tile
#define LT_SMEM (4 * LT_TILE * 2)           // 73728 bytes
#define NTRI    136                         // 16*17/2 lower-triangle tiles
__global__ __launch_bounds__(256, 2)
void mma_logits(const float* __restrict__ dscales, float* __restrict__ out) {
    extern __shared__ __align__(16) __nv_bfloat16 dsml[];
    int tid  = threadIdx.x;
    int warp = tid >> 5, lane = tid & 31;
    int bh = blockIdx.y;
    int h = bh & 15;

    // triangular index -> (it, jt) with jt <= it
    int L = blockIdx.x;
    int itt = (int)((sqrtf(8.f * (float)L + 1.f) - 1.f) * 0.5f);
    while ((itt + 1) * (itt + 2) / 2 <= L) itt++;
    while (itt * (itt + 1) / 2 > L) itt--;
    int jtt = L - itt * (itt + 1) / 2;
    int i0 = itt * 128;
    int j0 = jtt * 128;

    int wm = (warp & 3) * 32;
    int wn = (warp >> 2) * 64;

    size_t qbase = ((size_t)bh * Tt + i0) * DH;
    size_t kbase = ((size_t)bh * Tt + j0) * DH;
    const __nv_bfloat16* srcs[4] = { g_qh + qbase, g_ql + qbase, g_kh + kbase, g_kl + kbase };
    uint32_t sb = smem_u32(dsml);

#pragma unroll
    for (int t = 0; t < 4; t++) {
        const __nv_bfloat16* s = srcs[t];
#pragma unroll
        for (int it = 0; it < 4; it++) {
            int idx = tid + it * 256;
            int row = idx >> 3;
            int cc  = idx & 7;
            cp_async16(sb + (t * LT_TILE + row * SK + cc * 8) * 2,
                       s + (size_t)row * DH + cc * 8);
        }
    }
    CP_COMMIT();

    float c[16][4];
#pragma unroll
    for (int f = 0; f < 16; f++)
#pragma unroll
        for (int e = 0; e < 4; e++) c[f][e] = 0.f;

    int arow = lane & 15;
    int ablk = (lane >> 4) * 8;

    CP_WAIT0();
    __syncthreads();

#pragma unroll
    for (int ks = 0; ks < 64; ks += 16) {
        uint32_t a_hi[2][4], a_lo[2][4];
#pragma unroll
        for (int mf = 0; mf < 2; mf++) {
            uint32_t off = ((wm + mf * 16 + arow) * SK + ks + ablk) * 2;
            ldsm4(a_hi[mf], sb + 0 * LT_TILE * 2 + off);
            ldsm4(a_lo[mf], sb + 1 * LT_TILE * 2 + off);
        }
        uint32_t b_hi[8][2], b_lo[8][2];
#pragma unroll
        for (int pr = 0; pr < 4; pr++) {
            uint32_t off = ((wn + pr * 16 + arow) * SK + ks + ablk) * 2;
            uint32_t t4[4];
            ldsm4(t4, sb + 2 * LT_TILE * 2 + off);
            b_hi[pr*2+0][0] = t4[0]; b_hi[pr*2+0][1] = t4[2];
            b_hi[pr*2+1][0] = t4[1]; b_hi[pr*2+1][1] = t4[3];
            ldsm4(t4, sb + 3 * LT_TILE * 2 + off);
            b_lo[pr*2+0][0] = t4[0]; b_lo[pr*2+0][1] = t4[2];
            b_lo[pr*2+1][0] = t4[1]; b_lo[pr*2+1][1] = t4[3];
        }
#pragma unroll
        for (int mf = 0; mf < 2; mf++)
#pragma unroll
            for (int nf = 0; nf < 8; nf++) {
                mma_bf16(c[mf*8+nf], a_hi[mf], b_hi[nf]);
                mma_bf16(c[mf*8+nf], a_hi[mf], b_lo[nf]);
                mma_bf16(c[mf*8+nf], a_lo[mf], b_hi[nf]);
            }
    }

    float ds = dscales[h];
    int r = lane >> 2, q2 = (lane & 3) * 2;
    size_t abase = OFF_ATTN + (size_t)bh * Tt * Tt;
#pragma unroll
    for (int mf = 0; mf < 2; mf++)
#pragma unroll
        for (int nf = 0; nf < 8; nf++) {
            int i = i0 + wm + mf * 16 + r;
            int j = j0 + wn + nf * 8 + q2;
            float* f = c[mf*8+nf];
            float2 v0, v1;
            v0.x = f[0] * 0.125f - ds * (float)(i - j);
            v0.y = f[1] * 0.125f - ds * (float)(i - j - 1);
            v1.x = f[2] * 0.125f - ds * (float)(i + 8 - j);
            v1.y = f[3] * 0.125f - ds * (float)(i + 8 - j - 1);
            *(float2*)&out[abase + (size_t)i * Tt + j]       = v0;
            *(float2*)&out[abase + (size_t)(i + 8) * Tt + j] = v1;
        }
}

// ---------------- softmax + energies: register-resident, masked-lane MUFU skip ----------------
__global__ __launch_bounds__(256) void softmax_kernel(float* __restrict__ d_out) {
    __shared__ float red[4][8];
    int i   = blockIdx.x;
    int bh  = blockIdx.y;
    int tid = threadIdx.x;
    int lane = tid & 31, wid = tid >> 5;
    size_t arow = OFF_ATTN + ((size_t)bh * Tt + i) * Tt;

    float v[8];
    float lmax = -INFINITY;
#pragma unroll
    for (int k = 0; k < 4; k++) {
        int j = 2 * (tid + 256 * k);
        float a = -INFINITY, b = -INFINITY;
        if (j <= i) {
            float2 s = *(const float2*)&d_out[arow + j];
            a = s.x;
            if (j + 1 <= i) b = s.y;
        }
        v[2*k] = a; v[2*k+1] = b;
        lmax = fmaxf(lmax, fmaxf(a, b));
    }
#pragma unroll
    for (int off = 16; off > 0; off >>= 1)
        lmax = fmaxf(lmax, __shfl_xor_sync(0xFFFFFFFFu, lmax, off));
    if (lane == 0) red[0][wid] = lmax;
    __syncthreads();
    float m = red[0][0];
#pragma unroll
    for (int w = 1; w < 8; w++) m = fmaxf(m, red[0][w]);

    float lsum = 0.f;
#pragma unroll
    for (int k = 0; k < 4; k++) {
        int j = 2 * (tid + 256 * k);
        if (j <= i) {
            v[2*k] = __expf(v[2*k] - m);
            lsum += v[2*k];
            if (j + 1 <= i) { v[2*k+1] = __expf(v[2*k+1] - m); lsum += v[2*k+1]; }
            else v[2*k+1] = 0.f;
        } else { v[2*k] = 0.f; v[2*k+1] = 0.f; }
    }
#pragma unroll
    for (int off = 16; off > 0; off >>= 1)
        lsum += __shfl_xor_sync(0xFFFFFFFFu, lsum, off);
    if (lane == 0) red[1][wid] = lsum;
    __syncthreads();
    float tot = 0.f;
#pragma unroll
    for (int w = 0; w < 8; w++) tot += red[1][w];
    float inv = 1.f / tot;

    float de = 0.f, fe = 0.f;
#pragma unroll
    for (int k = 0; k < 4; k++) {
        int j = 2 * (tid + 256 * k);
        float a0 = 0.f, a1 = 0.f;
        if (j <= i) {
            a0 = v[2*k] * inv;
            de += a0 * (float)(i - j);
            fe -= a0 * __logf(a0 + 1e-9f);
            if (j + 1 <= i) {
                a1 = v[2*k+1] * inv;
                de += a1 * (float)(i - j - 1);
                fe -= a1 * __logf(a1 + 1e-9f);
            }
        }
        *(float2*)&d_out[arow + j] = make_float2(a0, a1);
    }
#pragma unroll
    for (int off = 16; off > 0; off >>= 1) {
        de += __shfl_xor_sync(0xFFFFFFFFu, de, off);
        fe += __shfl_xor_sync(0xFFFFFFFFu, fe, off);
    }
    if (lane == 0) { red[2][wid] = de; red[3][wid] = fe; }
    __syncthreads();
    if (tid == 0) {
        float sde = 0.f, sfe = 0.f;
#pragma unroll
        for (int w = 0; w < 8; w++) { sde += red[2][w]; sfe += red[3][w]; }
        atomicAdd(&d_out[OFF_DE], sde * (1.f / 65536.f));
        atomicAdd(&d_out[OFF_FE], sfe * (1.f / 65536.f));
    }
}

// ---------------- PV via warp-mma (occ 2): writes o split bf16 hi/lo ----------------
__global__ __launch_bounds__(256, 2) void pv_mma(const float* __restrict__ d_out_c) {
    __shared__ __align__(16) __nv_bfloat16 sAh[128 * SPAD];
    __shared__ __align__(16) __nv_bfloat16 sAl[128 * SPAD];
    __shared__ __align__(16) __nv_bfloat16 sVh[64 * SPAD];
    __shared__ __align__(16) __nv_bfloat16 sVl[64 * SPAD];
    int it = blockIdx.x;
    int bh = blockIdx.y;
    int b = bh >> 4, h = bh & 15;
    int i0 = it * 128;
    int tid  = threadIdx.x;
    int warp = tid >> 5, lane = tid & 31;
    int wm = (warp & 3) * 32;
    int wn = (warp >> 2) * 32;

    const float* Arow = d_out_c + OFF_ATTN + (size_t)bh * Tt * Tt;
    const float* Vb = g_qkv + (size_t)(b * Tt) * C3 + 2 * Cc + h * DH;

    uint32_t sbAh = smem_u32(sAh), sbAl = smem_u32(sAl);
    uint32_t sbVh = smem_u32(sVh), sbVl = smem_u32(sVl);

    float c[8][4];
#pragma unroll
    for (int f = 0; f < 8; f++)
#pragma unroll
        for (int e = 0; e < 4; e++) c[f][e] = 0.f;

    int arw = lane & 15;
    int ablk = (lane >> 4) * 8;
    int kmax = i0 + 128;

    for (int k0 = 0; k0 < kmax; k0 += 32) {
#pragma unroll
        for (int t = 0; t < 8; t++) {
            int idx = tid + t * 256;
            int row = idx >> 4;
            int cc  = idx & 15;
            float2 s = *(const float2*)&Arow[(size_t)(i0 + row) * Tt + k0 + cc * 2];
            __nv_bfloat16 h0 = __float2bfloat16(s.x);
            __nv_bfloat16 h1 = __float2bfloat16(s.y);
            __nv_bfloat162 hv; hv.x = h0; hv.y = h1;
            __nv_bfloat162 lv;
            lv.x = __float2bfloat16(s.x - __bfloat162float(h0));
            lv.y = __float2bfloat16(s.y - __bfloat162float(h1));
            *(__nv_bfloat162*)&sAh[row * SPAD + cc * 2] = hv;
            *(__nv_bfloat162*)&sAl[row * SPAD + cc * 2] = lv;
        }
#pragma unroll
        for (int t = 0; t < 8; t++) {
            int idx = tid + t * 256;
            int kk = idx >> 6;
            int d  = idx & 63;
            float xv = Vb[(size_t)(k0 + kk) * C3 + d];
            __nv_bfloat16 hh = __float2bfloat16(xv);
            sVh[d * SPAD + kk] = hh;
            sVl[d * SPAD + kk] = __float2bfloat16(xv - __bfloat162float(hh));
        }
        __syncthreads();

#pragma unroll
        for (int ks = 0; ks < 32; ks += 16) {
            uint32_t a_hi[2][4], a_lo[2][4];
#pragma unroll
            for (int mf = 0; mf < 2; mf++) {
                uint32_t off = ((wm + mf * 16 + arw) * SPAD + ks + ablk) * 2;
                ldsm4(a_hi[mf], sbAh + off);
                ldsm4(a_lo[mf], sbAl + off);
            }
            uint32_t b_hi[4][2], b_lo[4][2];
#pragma unroll
            for (int pr = 0; pr < 2; pr++) {
                uint32_t off = ((wn + pr * 16 + arw) * SPAD + ks + ablk) * 2;
                uint32_t t4[4];
                ldsm4(t4, sbVh + off);
                b_hi[pr*2+0][0] = t4[0]; b_hi[pr*2+0][1] = t4[2];
                b_hi[pr*2+1][0] = t4[1]; b_hi[pr*2+1][1] = t4[3];
                ldsm4(t4, sbVl + off);
                b_lo[pr*2+0][0] = t4[0]; b_lo[pr*2+0][1] = t4[2];
                b_lo[pr*2+1][0] = t4[1]; b_lo[pr*2+1][1] = t4[3];
            }
#pragma unroll
            for (int mf = 0; mf < 2; mf++)
#pragma unroll
                for (int nf = 0; nf < 4; nf++) {
                    mma_bf16(c[mf*4+nf], a_hi[mf], b_hi[nf]);
                    mma_bf16(c[mf*4+nf], a_hi[mf], b_lo[nf]);
                    mma_bf16(c[mf*4+nf], a_lo[mf], b_hi[nf]);
                }
        }
        __syncthreads();
    }

    int r = lane >> 2, q2 = (lane & 3) * 2;
#pragma unroll
    for (int mf = 0; mf < 2; mf++)
#pragma unroll
        for (int nf = 0; nf < 4; nf++) {
            int n = wn + nf * 8 + q2;
            float* f = c[mf*4+nf];
#pragma unroll
            for (int rr = 0; rr < 2; rr++) {
                int m = i0 + wm + mf * 16 + r + rr * 8;
                size_t dst = (size_t)(b * Tt + m) * Cc + h * DH + n;
                float v0 = f[rr*2+0], v1 = f[rr*2+1];
                __nv_bfloat16 h0 = __float2bfloat16(v0);
                __nv_bfloat16 h1 = __float2bfloat16(v1);
                __nv_bfloat162 hv; hv.x = h0; hv.y = h1;
                __nv_bfloat162 lv;
                lv.x = __float2bfloat16(v0 - __bfloat162float(h0));
                lv.y = __float2bfloat16(v1 - __bfloat162float(h1));
                *(__nv_bfloat162*)&g_ah[dst] = hv;
                *(__nv_bfloat162*)&g_al[dst] = lv;
            }
        }
}

// ---------------- launch ----------------
extern "C" void kernel_launch(void* const* d_in, const int* in_sizes, int n_in,
                              void* d_out, int out_size) {
    const float* x       = (const float*)d_in[0];
    const float* qkv_w   = (const float*)d_in[1];
    const float* proj_w  = (const float*)d_in[2];
    const float* dscales = (const float*)d_in[3];
    float* out = (float*)d_out;

    float *p_qkv;
    __nv_bfloat16 *p_ah, *p_al, *p_wh, *p_wl;
    cudaGetSymbolAddress((void**)&p_qkv, g_qkv);
    cudaGetSymbolAddress((void**)&p_ah,  g_ah);
    cudaGetSymbolAddress((void**)&p_al,  g_al);
    cudaGetSymbolAddress((void**)&p_wh,  g_wh);
    cudaGetSymbolAddress((void**)&p_wl,  g_wl);

    cudaFuncSetAttribute(mma_gemm_tn, cudaFuncAttributeMaxDynamicSharedMemorySize, GT_SMEM);
    cudaFuncSetAttribute(mma_logits,  cudaFuncAttributeMaxDynamicSharedMemorySize, LT_SMEM);

    // 1. dists + zero scalars (float2)
    dists_kernel<<<(unsigned)(((size_t)Tt * Tt / 2 + 255) / 256), 256>>>(out);

    // 2. split x and qkv_w to bf16 hi/lo (vectorized)
    cvt_split4<<<(BT * Cc / 4 + 255) / 256, 256>>>(x, p_ah, p_al, BT * Cc / 4);
    cvt_split4<<<(C3 * Cc / 4 + 255) / 256, 256>>>(qkv_w, p_wh, p_wl, C3 * Cc / 4);

    // 3. QKV GEMM (128x128, occ 2; mode 1: q/k split head-major, v fp32)
    {
        dim3 grid(C3 / 128, BT / 128);
        mma_gemm_tn<<<grid, 256, GT_SMEM>>>(p_ah, p_al, p_wh, p_wl, p_qkv, Cc, Cc, Cc, C3, 1);
    }

    // 4. logits (triangular grid warp mma, occ 2)
    {
        dim3 grid(NTRI, BH);
        mma_logits<<<grid, 256, LT_SMEM>>>(dscales, out);
    }

    // 5. row softmax + energies
    {
        dim3 grid(Tt, BH);
        softmax_kernel<<<grid, 256>>>(out);
    }

    // 6. PV -> o split bf16 directly into g_ah/g_al
    {
        dim3 grid(Tt / 128, BH);
        pv_mma<<<grid, 256>>>(out);
    }

    // 7. split proj_w, then proj GEMM (mode 0) -> out[0..N_OUT)
    cvt_split4<<<(Cc * Cc / 4 + 255) / 256, 256>>>(proj_w, p_wh, p_wl, Cc * Cc / 4);
    {
        dim3 grid(Cc / 128, BT / 128);
        mma_gemm_tn<<<grid, 256, GT_SMEM>>>(p_ah, p_al, p_wh, p_wl, out, Cc, Cc, Cc, Cc, 0);
    }
}